// round 10
// baseline (speedup 1.0000x reference)
#include <cuda_runtime.h>
#include <cstdint>

// Input:  x (2,8,256,256) fp32, F (3,3) fp32
// Output: (2,8,256,256) fp32 epipolar line-sum.
//
// Pipeline:
//  1) transpose_k : x -> g_t4[h][w][pg] (4-plane float4 chunks)
//  2) work_k      : blocks 0..511  = P & Q prefix tables (col+row)
//                   blocks 512..   = warp/pixel exact index + record emission
//  3) gather_k    : telescoped sum: one table load per record
//     record = ci | t<<8 | neg<<17 | isQ<<18
//     out = +P[c_last][T_end] - P[c_first][T_start] + sum of +/-Q[c][t] boundaries

#define FULLM 0xffffffffu
#define S_TAB (256 * 257)
#define RCAP  272                                  // records/pixel capacity (mult of 4)

__device__ float4   g_t4 [256 * 256 * 4];          // 4 MB repacked image
__device__ unsigned g_run[256 * 256 * RCAP];       // 71 MB record stream
__device__ int      g_nrun[256 * 256];
__device__ float4   g_tab[4 * S_TAB * 4];          // 16.8MB: [colP][colQ][rowP][rowQ]

__global__ void __launch_bounds__(256) transpose_k(const float* __restrict__ in) {
    int gid = blockIdx.x * 256 + threadIdx.x;
    int px = gid >> 2, pg = gid & 3;
    float4 o;
    o.x = __ldg(in + (pg * 4 + 0) * 65536 + px);
    o.y = __ldg(in + (pg * 4 + 1) * 65536 + px);
    o.z = __ldg(in + (pg * 4 + 2) * 65536 + px);
    o.w = __ldg(in + (pg * 4 + 3) * 65536 + px);
    g_t4[px * 4 + pg] = o;
}

// Exclusive prefix of one (region, line, pg). region: 0 colP, 1 colQ, 2 rowP, 3 rowQ.
// Q input = elementwise diff of line and line-1 (so Q[c][t] == P[c][t]-P[c-1][t]).
__device__ __forceinline__ void prefix_unit(int region, int line, int pg, int lane) {
    const bool isCol = region < 2;
    const bool isQ   = region & 1;
    float4* __restrict__ Pt = g_tab + (region * S_TAB + line * 257) * 4;

    if (isQ && line == 0) {                        // Q row 0 never read; zero for safety
        for (int t = lane; t < 257; t += 32)
            Pt[t * 4 + pg] = make_float4(0.f, 0.f, 0.f, 0.f);
        return;
    }
    float4 carry = make_float4(0.f, 0.f, 0.f, 0.f);
    if (lane == 0) Pt[pg] = carry;
#pragma unroll
    for (int r = 0; r < 8; ++r) {
        int t = r * 32 + lane;
        int px = isCol ? (line * 256 + t) : (t * 256 + line);
        float4 s = __ldg(g_t4 + px * 4 + pg);
        if (isQ) {
            int px2 = isCol ? (px - 256) : (px - 1);
            float4 s2 = __ldg(g_t4 + px2 * 4 + pg);
            s.x -= s2.x; s.y -= s2.y; s.z -= s2.z; s.w -= s2.w;
        }
#pragma unroll
        for (int d = 1; d < 32; d <<= 1) {
            float ax = __shfl_up_sync(FULLM, s.x, d);
            float ay = __shfl_up_sync(FULLM, s.y, d);
            float az = __shfl_up_sync(FULLM, s.z, d);
            float aw = __shfl_up_sync(FULLM, s.w, d);
            if (lane >= d) { s.x += ax; s.y += ay; s.z += az; s.w += aw; }
        }
        Pt[(t + 1) * 4 + pg] =
            make_float4(carry.x + s.x, carry.y + s.y, carry.z + s.z, carry.w + s.w);
        carry.x += __shfl_sync(FULLM, s.x, 31);
        carry.y += __shfl_sync(FULLM, s.y, 31);
        carry.z += __shfl_sync(FULLM, s.z, 31);
        carry.w += __shfl_sync(FULLM, s.w, 31);
    }
}

// Warp per pixel: EXACT index arithmetic (R4..R9 — do not touch) + record emission.
__device__ __forceinline__ void idx_rle_pixel(const float* __restrict__ Fm,
                                              int px, int lane) {
    const int w = px & 255, h = px >> 8;
    const float u = (float)w, v = (float)h;

    const float F0 = __ldg(Fm+0), F1 = __ldg(Fm+1), F2 = __ldg(Fm+2);
    const float F3 = __ldg(Fm+3), F4 = __ldg(Fm+4), F5 = __ldg(Fm+5);
    const float F6 = __ldg(Fm+6), F7 = __ldg(Fm+7), F8 = __ldg(Fm+8);
    float A = __fadd_rn(__fmaf_rn(F3, v, __fmul_rn(F0, u)), F6);
    float B = __fadd_rn(__fmaf_rn(F4, v, __fmul_rn(F1, u)), F7);
    float C = __fadd_rn(__fmaf_rn(F5, v, __fmul_rn(F2, u)), F8);

    const bool col = (fabsf(B) >= fabsf(A));
    float P, Q;
    if (col) { P = A; Q = (fabsf(B) < 1e-8f) ? 1e-8f : B; }
    else     { P = B; Q = (fabsf(A) < 1e-8f) ? 1e-8f : A; }
    const float rq  = __frcp_rn(Q);
    const float nrq = -rq;

    unsigned vals[8];
    float tf = (float)(lane * 8);
#pragma unroll
    for (int j = 0; j < 8; ++j, tf += 1.0f) {
        float n  = __fmaf_rn(P, tf, C);
        float yf = __fmul_rn(n, nrq);
        int   ci = __float2int_rn(yf);
        float d  = yf - (float)ci;
        if (0.5f - fabsf(d) < 5e-4f) {
            ci = __float2int_rn(__fdiv_rn(-n, Q));
        }
        vals[j] = ((unsigned)ci < 256u) ? (unsigned)ci : 0xFFFFu;
    }

    unsigned prev = __shfl_up_sync(FULLM, vals[7], 1);
    if (lane == 0) prev = 0xFFFFu;                 // before t=0: invalid

    // Count records this lane will emit.
    int cnt = 0;
    {
        unsigned p = prev;
#pragma unroll
        for (int k = 0; k < 8; ++k) {
            unsigned a = p, b = vals[k];
            if (a != b) {
                if (a == 0xFFFFu || b == 0xFFFFu) cnt += 1;
                else { int d = (int)b - (int)a; cnt += (d > 0) ? d : -d; }
            }
            p = b;
        }
    }
    if (lane == 31 && vals[7] != 0xFFFFu) cnt += 1;   // end record at t=256

    int off = cnt;
#pragma unroll
    for (int d = 1; d < 32; d <<= 1) {
        int o = __shfl_up_sync(FULLM, off, d);
        if (lane >= d) off += o;
    }
    int total = __shfl_sync(FULLM, off, 31);
    off -= cnt;
    if (lane == 31) g_nrun[px] = total;

    unsigned cur = (unsigned)px * RCAP + (unsigned)off;
    {
        unsigned p = prev;
#pragma unroll
        for (int k = 0; k < 8; ++k) {
            unsigned a = p, b = vals[k];
            unsigned t = (unsigned)(lane * 8 + k);
            if (a != b) {
                if (a == 0xFFFFu) {                  // start: -P[b][t]
                    g_run[cur++] = b | (t << 8) | (1u << 17);
                } else if (b == 0xFFFFu) {           // end:   +P[a][t]
                    g_run[cur++] = a | (t << 8);
                } else {
                    int d = (int)b - (int)a;
                    if (d > 0) {                     // up-steps: -Q[a+i][t]
                        for (int i = 1; i <= d; ++i)
                            g_run[cur++] = (a + (unsigned)i) | (t << 8) | (1u << 17) | (1u << 18);
                    } else {                         // down-steps: +Q[a-i][t]
                        for (int i = 0; i < -d; ++i)
                            g_run[cur++] = (a - (unsigned)i) | (t << 8) | (1u << 18);
                    }
                }
            }
            p = b;
        }
    }
    if (lane == 31 && vals[7] != 0xFFFFu)            // +P[c_last][256]
        g_run[cur++] = vals[7] | (256u << 8);
}

// blocks 0..511: 4096 prefix warps; blocks 512..8703: warp-per-pixel idx+records
__global__ void __launch_bounds__(256) work_k(const float* __restrict__ Fm) {
    const int lane = threadIdx.x & 31;
    const int warp = threadIdx.x >> 5;
    if (blockIdx.x < 512) {
        int wg = blockIdx.x * 8 + warp;              // 0..4095
        prefix_unit(wg >> 10, (wg >> 2) & 255, wg & 3, lane);
    } else {
        int px = (blockIdx.x - 512) * 8 + warp;
        idx_rle_pixel(Fm, px, lane);
    }
}

// Warp = 8 pixels x 4 channel-groups. One table load per record.
__global__ void __launch_bounds__(256) gather_k(const float* __restrict__ Fm,
                                                float* __restrict__ out) {
    const int lane = threadIdx.x & 31;
    const int warp = threadIdx.x >> 5;
    const int pg   = lane & 3;
    const int pix  = lane >> 2;
    const int w = blockIdx.y * 64 + warp * 8 + pix;
    const int h = blockIdx.x;
    const int px = h * 256 + w;
    const float u = (float)w, v = (float)h;

    // mode bit — exact same computation as idx_rle_pixel
    const float F0 = __ldg(Fm+0), F1 = __ldg(Fm+1);
    const float F3 = __ldg(Fm+3), F4 = __ldg(Fm+4);
    const float F6 = __ldg(Fm+6), F7 = __ldg(Fm+7);
    float A = __fadd_rn(__fmaf_rn(F3, v, __fmul_rn(F0, u)), F6);
    float B = __fadd_rn(__fmaf_rn(F4, v, __fmul_rn(F1, u)), F7);
    const bool col = (fabsf(B) >= fabsf(A));
    const int modeBase = col ? 0 : 2 * S_TAB;

    int n = __ldg(g_nrun + px);
    int nmax = n;
#pragma unroll
    for (int d = 16; d; d >>= 1)
        nmax = max(nmax, __shfl_xor_sync(FULLM, nmax, d));

    const uint4* __restrict__ rv =
        reinterpret_cast<const uint4*>(g_run + (size_t)px * RCAP);

    float4 acc0 = make_float4(0.f, 0.f, 0.f, 0.f);
    float4 acc1 = make_float4(0.f, 0.f, 0.f, 0.f);
    uint4 V = make_uint4(0u, 0u, 0u, 0u);
    for (int j = 0; j < nmax; ++j) {
        if (((j & 3) == 0) && (j < n)) V = __ldg(rv + (j >> 2));
        unsigned word = (j & 3) == 0 ? V.x : (j & 3) == 1 ? V.y
                       : (j & 3) == 2 ? V.z : V.w;
        if (j < n) {
            int   c  = word & 255;
            int   t  = (word >> 8) & 511;
            float s  = (word & (1u << 17)) ? -1.0f : 1.0f;
            int   kq = (word >> 18) & 1;
            int pos = modeBase + kq * S_TAB + c * 257 + t;
            float4 val = __ldg(g_tab + pos * 4 + pg);
            if (j & 1) {
                acc1.x = __fmaf_rn(s, val.x, acc1.x);
                acc1.y = __fmaf_rn(s, val.y, acc1.y);
                acc1.z = __fmaf_rn(s, val.z, acc1.z);
                acc1.w = __fmaf_rn(s, val.w, acc1.w);
            } else {
                acc0.x = __fmaf_rn(s, val.x, acc0.x);
                acc0.y = __fmaf_rn(s, val.y, acc0.y);
                acc0.z = __fmaf_rn(s, val.z, acc0.z);
                acc0.w = __fmaf_rn(s, val.w, acc0.w);
            }
        }
    }
    float4 acc = make_float4(acc0.x + acc1.x, acc0.y + acc1.y,
                             acc0.z + acc1.z, acc0.w + acc1.w);

    out[(pg * 4 + 0) * 65536 + px] = acc.x;
    out[(pg * 4 + 1) * 65536 + px] = acc.y;
    out[(pg * 4 + 2) * 65536 + px] = acc.z;
    out[(pg * 4 + 3) * 65536 + px] = acc.w;
}

extern "C" void kernel_launch(void* const* d_in, const int* in_sizes, int n_in,
                              void* d_out, int out_size) {
    const float* img = (const float*)d_in[0];
    const float* F   = (const float*)d_in[1];
    if (n_in >= 2 && in_sizes[0] == 9) {             // defensive: input order swap
        img = (const float*)d_in[1];
        F   = (const float*)d_in[0];
    }
    float* out = (float*)d_out;

    transpose_k<<<1024, 256>>>(img);
    work_k<<<8704, 256>>>(F);
    dim3 ggat(256, 4);
    gather_k<<<ggat, 256>>>(F, out);
}

// round 11
// speedup vs baseline: 1.2936x; 1.2936x over previous
#include <cuda_runtime.h>
#include <cstdint>

// Input:  x (2,8,256,256) fp32, F (3,3) fp32
// Output: (2,8,256,256) fp32 epipolar line-sum.
//
// Pipeline (R9 structure):
//  1) transpose_k : x -> g_t4[h][w][pg] (4-plane float4 chunks)
//  2) work_k      : blocks 0..255  = col+row exclusive prefix tables
//                   blocks 256..   = warp/pixel exact index + RLE (padded to 4)
//  3) gather_k    : 4 runs/block, 8 endpoint loads in flight, prefix diff

#define FULLM 0xffffffffu
#define RCAP  264                                  // run capacity/pixel (mult of 4)

__device__ float4   g_t4 [256 * 256 * 4];          // 4 MB   repacked image
__device__ unsigned g_run[256 * 256 * RCAP];       // runs: ci|t0<<9|t1<<18
__device__ int      g_nrun[256 * 256];             // padded run counts (mult of 4)
__device__ float4   g_pc [256 * 257 * 4];          // col prefix: line=h, t=w
__device__ float4   g_pr [256 * 257 * 4];          // row prefix: line=w, t=h

__global__ void __launch_bounds__(256) transpose_k(const float* __restrict__ in) {
    int gid = blockIdx.x * 256 + threadIdx.x;
    int px = gid >> 2, pg = gid & 3;
    float4 o;
    o.x = __ldg(in + (pg * 4 + 0) * 65536 + px);
    o.y = __ldg(in + (pg * 4 + 1) * 65536 + px);
    o.z = __ldg(in + (pg * 4 + 2) * 65536 + px);
    o.w = __ldg(in + (pg * 4 + 3) * 65536 + px);
    g_t4[px * 4 + pg] = o;
}

// Warp-serial exclusive prefix of one (line, pg) in direction dir.
__device__ __forceinline__ void prefix_line(int line, int pg, bool is_col, int lane) {
    float4* __restrict__ Pt = is_col ? g_pc : g_pr;
    float4 carry = make_float4(0.f, 0.f, 0.f, 0.f);
    if (lane == 0) Pt[(line * 257) * 4 + pg] = carry;
#pragma unroll
    for (int r = 0; r < 8; ++r) {
        int t = r * 32 + lane;
        int px = is_col ? (line * 256 + t) : (t * 256 + line);
        float4 s = __ldg(g_t4 + px * 4 + pg);
#pragma unroll
        for (int d = 1; d < 32; d <<= 1) {
            float ax = __shfl_up_sync(FULLM, s.x, d);
            float ay = __shfl_up_sync(FULLM, s.y, d);
            float az = __shfl_up_sync(FULLM, s.z, d);
            float aw = __shfl_up_sync(FULLM, s.w, d);
            if (lane >= d) { s.x += ax; s.y += ay; s.z += az; s.w += aw; }
        }
        Pt[(line * 257 + t + 1) * 4 + pg] =
            make_float4(carry.x + s.x, carry.y + s.y, carry.z + s.z, carry.w + s.w);
        carry.x += __shfl_sync(FULLM, s.x, 31);
        carry.y += __shfl_sync(FULLM, s.y, 31);
        carry.z += __shfl_sync(FULLM, s.z, 31);
        carry.w += __shfl_sync(FULLM, s.w, 31);
    }
}

// Warp per pixel: EXACT index arithmetic (R4..R9 — do not touch) + in-register RLE.
__device__ __forceinline__ void idx_rle_pixel(const float* __restrict__ Fm,
                                              int px, int lane) {
    const int w = px & 255, h = px >> 8;
    const float u = (float)w, v = (float)h;

    const float F0 = __ldg(Fm+0), F1 = __ldg(Fm+1), F2 = __ldg(Fm+2);
    const float F3 = __ldg(Fm+3), F4 = __ldg(Fm+4), F5 = __ldg(Fm+5);
    const float F6 = __ldg(Fm+6), F7 = __ldg(Fm+7), F8 = __ldg(Fm+8);
    float A = __fadd_rn(__fmaf_rn(F3, v, __fmul_rn(F0, u)), F6);
    float B = __fadd_rn(__fmaf_rn(F4, v, __fmul_rn(F1, u)), F7);
    float C = __fadd_rn(__fmaf_rn(F5, v, __fmul_rn(F2, u)), F8);

    const bool col = (fabsf(B) >= fabsf(A));
    float P, Q;
    if (col) { P = A; Q = (fabsf(B) < 1e-8f) ? 1e-8f : B; }
    else     { P = B; Q = (fabsf(A) < 1e-8f) ? 1e-8f : A; }
    const float rq  = __frcp_rn(Q);
    const float nrq = -rq;

    unsigned vals[8];
    float tf = (float)(lane * 8);
#pragma unroll
    for (int j = 0; j < 8; ++j, tf += 1.0f) {
        float n  = __fmaf_rn(P, tf, C);
        float yf = __fmul_rn(n, nrq);
        int   ci = __float2int_rn(yf);
        float d  = yf - (float)ci;
        if (0.5f - fabsf(d) < 5e-4f) {
            ci = __float2int_rn(__fdiv_rn(-n, Q));
        }
        vals[j] = ((unsigned)ci < 256u) ? (unsigned)ci : 0xFFFFu;
    }

    unsigned prev = __shfl_up_sync(FULLM, vals[7], 1);
    if (lane == 0) prev = 0x10000u;                 // t=0 always a run start

    unsigned m = 0, vm = 0;
#pragma unroll
    for (int k = 0; k < 8; ++k) {
        if (vals[k] != prev)      m  |= 1u << k;
        if (vals[k] != 0xFFFFu)   vm |= 1u << k;
        prev = vals[k];
    }

    unsigned cnt = __popc(m & vm);
    unsigned off = cnt;
#pragma unroll
    for (int d = 1; d < 32; d <<= 1) {
        unsigned o = __shfl_up_sync(FULLM, off, d);
        if (lane >= d) off += o;
    }
    unsigned total = __shfl_sync(FULLM, off, 31);
    off -= cnt;

    unsigned Bb = __ballot_sync(FULLM, m != 0);
    unsigned hmask = (lane == 31) ? 0u : (FULLM << (lane + 1));
    unsigned nb = Bb & hmask;
    int nl = nb ? (__ffs(nb) - 1) : lane;
    unsigned m2 = __shfl_sync(FULLM, m, nl);
    int cross_t1 = nb ? (nl * 8 + __ffs(m2) - 1) : 256;

    unsigned base = (unsigned)px * RCAP + off;
#pragma unroll
    for (int k = 0; k < 8; ++k) {
        if (((m >> k) & 1u) && ((vm >> k) & 1u)) {
            unsigned rem = m >> (k + 1);
            int t1 = rem ? (lane * 8 + k + 1 + __ffs(rem) - 1) : cross_t1;
            int t0 = lane * 8 + k;
            g_run[base++] = vals[k] | ((unsigned)t0 << 9) | ((unsigned)t1 << 18);
        }
    }

    // Pad to multiple of 4 with null runs (ci=0,t0=t1=0 -> diff == 0 exactly).
    if (lane == 31) {
        unsigned padded = (total + 3u) & ~3u;
        g_nrun[px] = (int)padded;
        unsigned pbase = (unsigned)px * RCAP;
        for (unsigned i = total; i < padded; ++i) g_run[pbase + i] = 0u;
    }
}

// blocks 0..255: 2048 prefix warps (dir x 256 lines x 4 pg)
// blocks 256..8447: warp-per-pixel index+RLE (65536 pixels)
__global__ void __launch_bounds__(256) work_k(const float* __restrict__ Fm) {
    const int lane = threadIdx.x & 31;
    const int warp = threadIdx.x >> 5;
    if (blockIdx.x < 256) {
        int wg = blockIdx.x * 8 + warp;             // 0..2047
        prefix_line((wg >> 2) & 255, wg & 3, wg < 1024, lane);
    } else {
        int px = (blockIdx.x - 256) * 8 + warp;     // 0..65535
        idx_rle_pixel(Fm, px, lane);
    }
}

// Warp = 8 pixels x 4 channel-groups. 4 runs per block, 8 endpoint loads in flight.
__global__ void __launch_bounds__(256) gather_k(const float* __restrict__ Fm,
                                                float* __restrict__ out) {
    const int lane = threadIdx.x & 31;
    const int warp = threadIdx.x >> 5;
    const int pg   = lane & 3;
    const int pix  = lane >> 2;
    const int w = blockIdx.y * 64 + warp * 8 + pix;
    const int h = blockIdx.x;
    const int px = h * 256 + w;
    const float u = (float)w, v = (float)h;

    // mode bit — exact same computation as idx_rle_pixel
    const float F0 = __ldg(Fm+0), F1 = __ldg(Fm+1);
    const float F3 = __ldg(Fm+3), F4 = __ldg(Fm+4);
    const float F6 = __ldg(Fm+6), F7 = __ldg(Fm+7);
    float A = __fadd_rn(__fmaf_rn(F3, v, __fmul_rn(F0, u)), F6);
    float B = __fadd_rn(__fmaf_rn(F4, v, __fmul_rn(F1, u)), F7);
    const bool col = (fabsf(B) >= fabsf(A));
    const float4* __restrict__ Ptab = (col ? g_pc : g_pr) + pg;

    int n = __ldg(g_nrun + px);                    // multiple of 4
    int nmax = n;
#pragma unroll
    for (int d = 16; d; d >>= 1)
        nmax = max(nmax, __shfl_xor_sync(FULLM, nmax, d));
    int nb   = n >> 2;
    int nbmx = nmax >> 2;

    const uint4* __restrict__ rv =
        reinterpret_cast<const uint4*>(g_run + (size_t)px * RCAP);

    float4 acc0 = make_float4(0.f, 0.f, 0.f, 0.f);
    float4 acc1 = make_float4(0.f, 0.f, 0.f, 0.f);
    for (int b = 0; b < nbmx; ++b) {
        if (b < nb) {
            uint4 V = __ldg(rv + b);
            // decode all 4 runs, then issue all 8 endpoint loads (MLP 8)
            int c0 =  V.x & 511, a0 = (V.x >> 9) & 511, b0 = V.x >> 18;
            int c1 =  V.y & 511, a1 = (V.y >> 9) & 511, b1 = V.y >> 18;
            int c2 =  V.z & 511, a2 = (V.z >> 9) & 511, b2 = V.z >> 18;
            int c3 =  V.w & 511, a3 = (V.w >> 9) & 511, b3 = V.w >> 18;
            float4 l0 = __ldg(Ptab + (c0 * 257 + a0) * 4);
            float4 h0 = __ldg(Ptab + (c0 * 257 + b0) * 4);
            float4 l1 = __ldg(Ptab + (c1 * 257 + a1) * 4);
            float4 h1 = __ldg(Ptab + (c1 * 257 + b1) * 4);
            float4 l2 = __ldg(Ptab + (c2 * 257 + a2) * 4);
            float4 h2 = __ldg(Ptab + (c2 * 257 + b2) * 4);
            float4 l3 = __ldg(Ptab + (c3 * 257 + a3) * 4);
            float4 h3 = __ldg(Ptab + (c3 * 257 + b3) * 4);
            acc0.x += h0.x - l0.x; acc0.y += h0.y - l0.y;
            acc0.z += h0.z - l0.z; acc0.w += h0.w - l0.w;
            acc1.x += h1.x - l1.x; acc1.y += h1.y - l1.y;
            acc1.z += h1.z - l1.z; acc1.w += h1.w - l1.w;
            acc0.x += h2.x - l2.x; acc0.y += h2.y - l2.y;
            acc0.z += h2.z - l2.z; acc0.w += h2.w - l2.w;
            acc1.x += h3.x - l3.x; acc1.y += h3.y - l3.y;
            acc1.z += h3.z - l3.z; acc1.w += h3.w - l3.w;
        }
    }
    float4 acc = make_float4(acc0.x + acc1.x, acc0.y + acc1.y,
                             acc0.z + acc1.z, acc0.w + acc1.w);

    out[(pg * 4 + 0) * 65536 + px] = acc.x;
    out[(pg * 4 + 1) * 65536 + px] = acc.y;
    out[(pg * 4 + 2) * 65536 + px] = acc.z;
    out[(pg * 4 + 3) * 65536 + px] = acc.w;
}

extern "C" void kernel_launch(void* const* d_in, const int* in_sizes, int n_in,
                              void* d_out, int out_size) {
    const float* img = (const float*)d_in[0];
    const float* F   = (const float*)d_in[1];
    if (n_in >= 2 && in_sizes[0] == 9) {            // defensive: input order swap
        img = (const float*)d_in[1];
        F   = (const float*)d_in[0];
    }
    float* out = (float*)d_out;

    transpose_k<<<1024, 256>>>(img);
    work_k<<<8448, 256>>>(F);
    dim3 ggat(256, 4);
    gather_k<<<ggat, 256>>>(F, out);
}

// round 12
// speedup vs baseline: 1.3960x; 1.0792x over previous
#include <cuda_runtime.h>
#include <cstdint>

// Input:  x (2,8,256,256) fp32, F (3,3) fp32
// Output: (2,8,256,256) fp32 epipolar line-sum.
//
// Pipeline (R9 structure; gather retiled to 8x8 pixel blocks for L1 reuse):
//  1) transpose_k : x -> g_t4[h][w][pg] (4-plane float4 chunks)
//  2) work_k      : blocks 0..255  = col+row exclusive prefix tables
//                   blocks 256..   = warp-per-pixel exact index + in-register RLE
//  3) gather_k    : per run: acc += P[ci][t1] - P[ci][t0]   (2 loads/run)

#define FULLM 0xffffffffu

__device__ float4   g_t4 [256 * 256 * 4];        // 4 MB   repacked image
__device__ unsigned g_run[256 * 256 * 264];      // 69 MB  packed runs: ci|t0<<9|t1<<18
__device__ int      g_nrun[256 * 256];
__device__ float4   g_pc [256 * 257 * 4];        // 4.2MB  col prefix: line=h, t=w
__device__ float4   g_pr [256 * 257 * 4];        // 4.2MB  row prefix: line=w, t=h

__global__ void __launch_bounds__(256) transpose_k(const float* __restrict__ in) {
    int gid = blockIdx.x * 256 + threadIdx.x;    // 262144 = 65536 px * 4 groups
    int px = gid >> 2, pg = gid & 3;
    float4 o;
    o.x = __ldg(in + (pg * 4 + 0) * 65536 + px);
    o.y = __ldg(in + (pg * 4 + 1) * 65536 + px);
    o.z = __ldg(in + (pg * 4 + 2) * 65536 + px);
    o.w = __ldg(in + (pg * 4 + 3) * 65536 + px);
    g_t4[px * 4 + pg] = o;
}

// Warp-serial exclusive prefix of one (line, pg) in direction dir.
__device__ __forceinline__ void prefix_line(int line, int pg, bool is_col, int lane) {
    float4* __restrict__ Pt = is_col ? g_pc : g_pr;
    float4 carry = make_float4(0.f, 0.f, 0.f, 0.f);
    if (lane == 0) Pt[(line * 257) * 4 + pg] = carry;
#pragma unroll
    for (int r = 0; r < 8; ++r) {
        int t = r * 32 + lane;
        int px = is_col ? (line * 256 + t) : (t * 256 + line);
        float4 s = __ldg(g_t4 + px * 4 + pg);
#pragma unroll
        for (int d = 1; d < 32; d <<= 1) {
            float ax = __shfl_up_sync(FULLM, s.x, d);
            float ay = __shfl_up_sync(FULLM, s.y, d);
            float az = __shfl_up_sync(FULLM, s.z, d);
            float aw = __shfl_up_sync(FULLM, s.w, d);
            if (lane >= d) { s.x += ax; s.y += ay; s.z += az; s.w += aw; }
        }
        Pt[(line * 257 + t + 1) * 4 + pg] =
            make_float4(carry.x + s.x, carry.y + s.y, carry.z + s.z, carry.w + s.w);
        carry.x += __shfl_sync(FULLM, s.x, 31);
        carry.y += __shfl_sync(FULLM, s.y, 31);
        carry.z += __shfl_sync(FULLM, s.z, 31);
        carry.w += __shfl_sync(FULLM, s.w, 31);
    }
}

// Warp per pixel: EXACT index arithmetic (R4..R9 — do not touch) + in-register RLE.
__device__ __forceinline__ void idx_rle_pixel(const float* __restrict__ Fm,
                                              int px, int lane) {
    const int w = px & 255, h = px >> 8;
    const float u = (float)w, v = (float)h;

    const float F0 = __ldg(Fm+0), F1 = __ldg(Fm+1), F2 = __ldg(Fm+2);
    const float F3 = __ldg(Fm+3), F4 = __ldg(Fm+4), F5 = __ldg(Fm+5);
    const float F6 = __ldg(Fm+6), F7 = __ldg(Fm+7), F8 = __ldg(Fm+8);
    float A = __fadd_rn(__fmaf_rn(F3, v, __fmul_rn(F0, u)), F6);
    float B = __fadd_rn(__fmaf_rn(F4, v, __fmul_rn(F1, u)), F7);
    float C = __fadd_rn(__fmaf_rn(F5, v, __fmul_rn(F2, u)), F8);

    const bool col = (fabsf(B) >= fabsf(A));
    float P, Q;
    if (col) { P = A; Q = (fabsf(B) < 1e-8f) ? 1e-8f : B; }
    else     { P = B; Q = (fabsf(A) < 1e-8f) ? 1e-8f : A; }
    const float rq  = __frcp_rn(Q);
    const float nrq = -rq;

    unsigned vals[8];
    float tf = (float)(lane * 8);
#pragma unroll
    for (int j = 0; j < 8; ++j, tf += 1.0f) {
        float n  = __fmaf_rn(P, tf, C);
        float yf = __fmul_rn(n, nrq);
        int   ci = __float2int_rn(yf);
        float d  = yf - (float)ci;
        if (0.5f - fabsf(d) < 5e-4f) {
            ci = __float2int_rn(__fdiv_rn(-n, Q));
        }
        vals[j] = ((unsigned)ci < 256u) ? (unsigned)ci : 0xFFFFu;
    }

    unsigned prev = __shfl_up_sync(FULLM, vals[7], 1);
    if (lane == 0) prev = 0x10000u;                 // t=0 always a run start

    unsigned m = 0, vm = 0;
#pragma unroll
    for (int k = 0; k < 8; ++k) {
        if (vals[k] != prev)      m  |= 1u << k;
        if (vals[k] != 0xFFFFu)   vm |= 1u << k;
        prev = vals[k];
    }

    unsigned cnt = __popc(m & vm);
    unsigned off = cnt;
#pragma unroll
    for (int d = 1; d < 32; d <<= 1) {
        unsigned o = __shfl_up_sync(FULLM, off, d);
        if (lane >= d) off += o;
    }
    unsigned total = __shfl_sync(FULLM, off, 31);
    off -= cnt;
    if (lane == 31) g_nrun[px] = (int)total;

    unsigned Bb = __ballot_sync(FULLM, m != 0);
    unsigned hmask = (lane == 31) ? 0u : (FULLM << (lane + 1));
    unsigned nb = Bb & hmask;
    int nl = nb ? (__ffs(nb) - 1) : lane;
    unsigned m2 = __shfl_sync(FULLM, m, nl);
    int cross_t1 = nb ? (nl * 8 + __ffs(m2) - 1) : 256;

    unsigned base = (unsigned)px * 264u + off;
#pragma unroll
    for (int k = 0; k < 8; ++k) {
        if (((m >> k) & 1u) && ((vm >> k) & 1u)) {
            unsigned rem = m >> (k + 1);
            int t1 = rem ? (lane * 8 + k + 1 + __ffs(rem) - 1) : cross_t1;
            int t0 = lane * 8 + k;
            g_run[base++] = vals[k] | ((unsigned)t0 << 9) | ((unsigned)t1 << 18);
        }
    }
}

// blocks 0..255: 2048 prefix warps (dir x 256 lines x 4 pg)
// blocks 256..8447: warp-per-pixel index+RLE (65536 pixels)
__global__ void __launch_bounds__(256) work_k(const float* __restrict__ Fm) {
    const int lane = threadIdx.x & 31;
    const int warp = threadIdx.x >> 5;
    if (blockIdx.x < 256) {
        int wg = blockIdx.x * 8 + warp;             // 0..2047
        prefix_line((wg >> 2) & 255, wg & 3, wg < 1024, lane);
    } else {
        int px = (blockIdx.x - 256) * 8 + warp;     // 0..65535
        idx_rle_pixel(Fm, px, lane);
    }
}

// Block = 8x8 pixel tile (8 warps x 8 pixels): cross-h table reuse in L1.
// Warp = 8 pixels x 4 channel-groups. Per run: 2 endpoint loads, prefix diff.
__global__ void __launch_bounds__(256) gather_k(const float* __restrict__ Fm,
                                                float* __restrict__ out) {
    const int lane = threadIdx.x & 31;
    const int warp = threadIdx.x >> 5;
    const int pg   = lane & 3;
    const int pix  = lane >> 2;
    const int h = blockIdx.x * 8 + warp;            // 8 h rows per block
    const int w = blockIdx.y * 8 + pix;             // 8 w cols per warp
    const int px = h * 256 + w;
    const float u = (float)w, v = (float)h;

    // mode bit — exact same computation as idx_rle_pixel
    const float F0 = __ldg(Fm+0), F1 = __ldg(Fm+1);
    const float F3 = __ldg(Fm+3), F4 = __ldg(Fm+4);
    const float F6 = __ldg(Fm+6), F7 = __ldg(Fm+7);
    float A = __fadd_rn(__fmaf_rn(F3, v, __fmul_rn(F0, u)), F6);
    float B = __fadd_rn(__fmaf_rn(F4, v, __fmul_rn(F1, u)), F7);
    const bool col = (fabsf(B) >= fabsf(A));
    const float4* __restrict__ Ptab = col ? g_pc : g_pr;

    int n = __ldg(g_nrun + px);
    int nmax = n;
#pragma unroll
    for (int d = 16; d; d >>= 1)
        nmax = max(nmax, __shfl_xor_sync(FULLM, nmax, d));

    const uint4* __restrict__ rv =
        reinterpret_cast<const uint4*>(g_run + (size_t)px * 264u);

    float4 acc = make_float4(0.f, 0.f, 0.f, 0.f);
    uint4 V = make_uint4(0u, 0u, 0u, 0u);
    for (int j = 0; j < nmax; ++j) {
        if ((j & 3) == 0) V = __ldg(rv + (j >> 2));
        unsigned word = (j & 3) == 0 ? V.x : (j & 3) == 1 ? V.y
                       : (j & 3) == 2 ? V.z : V.w;
        if (j < n) {
            int ci = word & 511;
            int t0 = (word >> 9) & 511;
            int t1 = word >> 18;
            float4 lo = __ldg(Ptab + (ci * 257 + t0) * 4 + pg);
            float4 hi = __ldg(Ptab + (ci * 257 + t1) * 4 + pg);
            acc.x += hi.x - lo.x;
            acc.y += hi.y - lo.y;
            acc.z += hi.z - lo.z;
            acc.w += hi.w - lo.w;
        }
    }

    out[(pg * 4 + 0) * 65536 + px] = acc.x;
    out[(pg * 4 + 1) * 65536 + px] = acc.y;
    out[(pg * 4 + 2) * 65536 + px] = acc.z;
    out[(pg * 4 + 3) * 65536 + px] = acc.w;
}

extern "C" void kernel_launch(void* const* d_in, const int* in_sizes, int n_in,
                              void* d_out, int out_size) {
    const float* img = (const float*)d_in[0];
    const float* F   = (const float*)d_in[1];
    if (n_in >= 2 && in_sizes[0] == 9) {            // defensive: input order swap
        img = (const float*)d_in[1];
        F   = (const float*)d_in[0];
    }
    float* out = (float*)d_out;

    transpose_k<<<1024, 256>>>(img);
    work_k<<<8448, 256>>>(F);
    dim3 ggat(32, 32);
    gather_k<<<ggat, 256>>>(F, out);
}